// round 9
// baseline (speedup 1.0000x reference)
#include <cuda_runtime.h>
#include <cuda_bf16.h>
#include <cstdint>

#define N_NODES 50000
#define DIM 128
#define N_EDGES 800000
#define N_OUT 47

// ---------------- scratch (device globals; no allocation allowed) ----------------
// features stored as split bf16: value = hi + lo  (hi = bf16(x), lo = bf16(x - hi))
__device__ __align__(16) __nv_bfloat16 g_f0hi[N_NODES * DIM];
__device__ __align__(16) __nv_bfloat16 g_f0lo[N_NODES * DIM];
__device__ __align__(16) __nv_bfloat16 g_f1hi[N_NODES * DIM];
__device__ __align__(16) __nv_bfloat16 g_f1lo[N_NODES * DIM];
__device__ __align__(16) __nv_bfloat16 g_mhi[N_NODES * DIM];
__device__ __align__(16) __nv_bfloat16 g_mlo[N_NODES * DIM];
__device__ int   g_rowptr[N_NODES + 1];
__device__ __align__(16) int g_cursor[N_NODES];
__device__ int   g_esrc[N_EDGES];
__device__ __align__(16) __nv_bfloat16 g_Bhi[128 * 256];  // weights hi, row-major [N][256]
__device__ __align__(16) __nv_bfloat16 g_Blo[128 * 256];  // weights lo

// ---------------- helpers ----------------

__device__ __forceinline__ uint32_t pack_bf16(__nv_bfloat16 l, __nv_bfloat16 h) {
    return ((uint32_t)__bfloat16_as_ushort(h) << 16) | __bfloat16_as_ushort(l);
}
__device__ __forceinline__ float bf_lo(uint32_t w) { return __uint_as_float(w << 16); }
__device__ __forceinline__ float bf_hi(uint32_t w) { return __uint_as_float(w & 0xFFFF0000u); }

__device__ __forceinline__ void split2(float v0, float v1, uint32_t& hi, uint32_t& lo) {
    __nv_bfloat16 h0 = __float2bfloat16(v0), h1 = __float2bfloat16(v1);
    __nv_bfloat16 l0 = __float2bfloat16(v0 - __bfloat162float(h0));
    __nv_bfloat16 l1 = __float2bfloat16(v1 - __bfloat162float(h1));
    hi = pack_bf16(h0, h1);
    lo = pack_bf16(l0, l1);
}

// ---------------- CSR build (by dst) ----------------

__global__ void zero_cursor_k() {
    int i = blockIdx.x * blockDim.x + threadIdx.x;
    if (i < N_NODES / 4) ((int4*)g_cursor)[i] = make_int4(0, 0, 0, 0);
}
__global__ void count_k(const int* __restrict__ dst) {
    int e = blockIdx.x * blockDim.x + threadIdx.x;
    if (e < N_EDGES) atomicAdd(&g_cursor[dst[e]], 1);
}
__global__ void scan_k() {
    __shared__ int ssum[1024];
    int t = threadIdx.x;
    const int CH = (N_NODES + 1023) / 1024;
    int base = t * CH;
    int s = 0;
    for (int i = 0; i < CH; i++) { int idx = base + i; if (idx < N_NODES) s += g_cursor[idx]; }
    ssum[t] = s;
    __syncthreads();
    for (int off = 1; off < 1024; off <<= 1) {
        int v = 0;
        if (t >= off) v = ssum[t - off];
        __syncthreads();
        if (t >= off) ssum[t] += v;
        __syncthreads();
    }
    int run = (t == 0) ? 0 : ssum[t - 1];
    for (int i = 0; i < CH; i++) {
        int idx = base + i;
        if (idx < N_NODES) {
            int c = g_cursor[idx];
            g_rowptr[idx] = run;
            g_cursor[idx] = run;
            run += c;
        }
    }
    if (t == 0) g_rowptr[N_NODES] = N_EDGES;
}
__global__ void bucket_k(const int* __restrict__ src, const int* __restrict__ dst) {
    int e = blockIdx.x * blockDim.x + threadIdx.x;
    if (e < N_EDGES) {
        int pos = atomicAdd(&g_cursor[dst[e]], 1);
        g_esrc[pos] = src[e];
    }
}

// ---------------- mean aggregation: one warp per node; writes packed hi/lo mean ----------------

template <bool GF32>
__global__ void agg_k(const float* __restrict__ xf,
                      const __nv_bfloat16* __restrict__ hhi,
                      const __nv_bfloat16* __restrict__ hlo) {
    int gt = blockIdx.x * blockDim.x + threadIdx.x;
    int node = gt >> 5, lane = gt & 31;
    if (node >= N_NODES) return;
    int beg = g_rowptr[node], end = g_rowptr[node + 1];
    float a0 = 0.f, a1 = 0.f, a2 = 0.f, a3 = 0.f;
    float c0 = 0.f, c1 = 0.f, c2 = 0.f, c3 = 0.f;
    int j = beg;
    if (GF32) {
        for (; j + 1 < end; j += 2) {
            int s0 = g_esrc[j], s1 = g_esrc[j + 1];
            float4 v0 = *(const float4*)(xf + (size_t)s0 * DIM + lane * 4);
            float4 v1 = *(const float4*)(xf + (size_t)s1 * DIM + lane * 4);
            a0 += v0.x; a1 += v0.y; a2 += v0.z; a3 += v0.w;
            c0 += v1.x; c1 += v1.y; c2 += v1.z; c3 += v1.w;
        }
        if (j < end) {
            int s0 = g_esrc[j];
            float4 v0 = *(const float4*)(xf + (size_t)s0 * DIM + lane * 4);
            a0 += v0.x; a1 += v0.y; a2 += v0.z; a3 += v0.w;
        }
    } else {
        for (; j + 1 < end; j += 2) {
            int s0 = g_esrc[j], s1 = g_esrc[j + 1];
            uint2 h0 = *(const uint2*)(hhi + (size_t)s0 * DIM + lane * 4);
            uint2 l0 = *(const uint2*)(hlo + (size_t)s0 * DIM + lane * 4);
            uint2 h1 = *(const uint2*)(hhi + (size_t)s1 * DIM + lane * 4);
            uint2 l1 = *(const uint2*)(hlo + (size_t)s1 * DIM + lane * 4);
            a0 += bf_lo(h0.x) + bf_lo(l0.x); a1 += bf_hi(h0.x) + bf_hi(l0.x);
            a2 += bf_lo(h0.y) + bf_lo(l0.y); a3 += bf_hi(h0.y) + bf_hi(l0.y);
            c0 += bf_lo(h1.x) + bf_lo(l1.x); c1 += bf_hi(h1.x) + bf_hi(l1.x);
            c2 += bf_lo(h1.y) + bf_lo(l1.y); c3 += bf_hi(h1.y) + bf_hi(l1.y);
        }
        if (j < end) {
            int s0 = g_esrc[j];
            uint2 h0 = *(const uint2*)(hhi + (size_t)s0 * DIM + lane * 4);
            uint2 l0 = *(const uint2*)(hlo + (size_t)s0 * DIM + lane * 4);
            a0 += bf_lo(h0.x) + bf_lo(l0.x); a1 += bf_hi(h0.x) + bf_hi(l0.x);
            a2 += bf_lo(h0.y) + bf_lo(l0.y); a3 += bf_hi(h0.y) + bf_hi(l0.y);
        }
    }
    float inv = 1.f / fmaxf((float)(end - beg), 1.f);
    a0 = (a0 + c0) * inv; a1 = (a1 + c1) * inv;
    a2 = (a2 + c2) * inv; a3 = (a3 + c3) * inv;
    uint32_t h01, l01, h23, l23;
    split2(a0, a1, h01, l01);
    split2(a2, a3, h23, l23);
    size_t off = (size_t)node * DIM + lane * 4;
    *(uint32_t*)(g_mhi + off) = h01;
    *(uint32_t*)(g_mhi + off + 2) = h23;
    *(uint32_t*)(g_mlo + off) = l01;
    *(uint32_t*)(g_mlo + off + 2) = l23;
}

// ---------------- B prep: W[n][k] -> hi/lo bf16 row-major [NT][256] ----------------

__global__ void prepB_k(const float* __restrict__ ws, const float* __restrict__ wn,
                        int nout, int NT) {
    int idx = blockIdx.x * blockDim.x + threadIdx.x;
    if (idx >= NT * 256) return;
    int n = idx / 256, k = idx % 256;
    float v = 0.f;
    if (n < nout) v = (k < 128) ? ws[n * 128 + k] : wn[n * 128 + (k - 128)];
    __nv_bfloat16 h = __float2bfloat16(v);
    __nv_bfloat16 l = __float2bfloat16(v - __bfloat162float(h));
    g_Bhi[idx] = h;
    g_Blo[idx] = l;
}

// ---------------- mma.sync split-bf16 GEMM ----------------
// 256 thr = 8 warps (4m x 2n). CTA tile 128 x BN, BK=32. m16n8k16 bf16 HMMA, fp32 accum.
// 3 passes: Ahi*Bhi + Ahi*Blo + Alo*Bhi. A/B staged via register prefetch.

__device__ __forceinline__ void mma16816(float* c, const uint32_t* a, const uint32_t* b) {
    asm volatile(
        "mma.sync.aligned.m16n8k16.row.col.f32.bf16.bf16.f32 "
        "{%0,%1,%2,%3}, {%4,%5,%6,%7}, {%8,%9}, {%0,%1,%2,%3};"
        : "+f"(c[0]), "+f"(c[1]), "+f"(c[2]), "+f"(c[3])
        : "r"(a[0]), "r"(a[1]), "r"(a[2]), "r"(a[3]), "r"(b[0]), "r"(b[1]));
}

#define BKP 40  // padded row: 32 bf16 + 8 (stride 80B -> conflict-free frags)

template <int BN, int NOUT, bool RELU, bool L1, bool OUTP>
__global__ void __launch_bounds__(256) gemm_mma(
    const float* __restrict__ xf,
    const __nv_bfloat16* __restrict__ Ahi, const __nv_bfloat16* __restrict__ Alo,
    const float* __restrict__ bias,
    float* __restrict__ outf,
    __nv_bfloat16* __restrict__ outHi, __nv_bfloat16* __restrict__ outLo) {
    constexpr int HN = BN / 2;
    constexpr int NF = HN / 8;
    constexpr int BITER = BN / 32;  // B uint2s per thread
    __shared__ __align__(16) uint16_t As_hi[128][BKP];
    __shared__ __align__(16) uint16_t As_lo[128][BKP];
    __shared__ __align__(16) uint16_t Bs_hi[BN][BKP];
    __shared__ __align__(16) uint16_t Bs_lo[BN][BKP];

    int tid = threadIdx.x;
    int warp = tid >> 5, lane = tid & 31;
    int wm = warp & 3, wn = warp >> 2;
    int qrow = lane >> 2, qk2 = (lane & 3) * 2;
    int rowBase = blockIdx.x * 128;

    float c[2][NF][4];
#pragma unroll
    for (int mi = 0; mi < 2; mi++)
#pragma unroll
        for (int ni = 0; ni < NF; ni++)
#pragma unroll
            for (int j = 0; j < 4; j++) c[mi][ni][j] = 0.f;

    uint2 rah[4], ral[4], rbh[BITER], rbl[BITER];
    int ar = tid >> 3, au = tid & 7;  // A: thread handles rows ar, ar+32, ar+64, ar+96? no: idx mapping below

    // ---- load helpers (registers) ----
    auto loadA = [&](int kb) {
        if (L1 && kb < 128) {
#pragma unroll
            for (int i = 0; i < 4; i++) {
                int idx = tid + i * 256;
                int r = idx >> 3, u = idx & 7;
                int gr = rowBase + r;
                if (gr >= N_NODES) gr = N_NODES - 1;
                float4 v = *(const float4*)(xf + (size_t)gr * 128 + kb + u * 4);
                split2(v.x, v.y, rah[i].x, ral[i].x);
                split2(v.z, v.w, rah[i].y, ral[i].y);
            }
        } else {
            const __nv_bfloat16* sh = (kb < 128) ? Ahi + kb : g_mhi + (kb - 128);
            const __nv_bfloat16* sl = (kb < 128) ? Alo + kb : g_mlo + (kb - 128);
#pragma unroll
            for (int i = 0; i < 4; i++) {
                int idx = tid + i * 256;
                int r = idx >> 3, u = idx & 7;
                int gr = rowBase + r;
                if (gr >= N_NODES) gr = N_NODES - 1;
                rah[i] = *(const uint2*)(sh + (size_t)gr * 128 + u * 4);
                ral[i] = *(const uint2*)(sl + (size_t)gr * 128 + u * 4);
            }
        }
    };
    auto loadB = [&](int kb) {
#pragma unroll
        for (int i = 0; i < BITER; i++) {
            int idx = tid + i * 256;
            int n = idx >> 3, u = idx & 7;
            rbh[i] = *(const uint2*)(g_Bhi + n * 256 + kb + u * 4);
            rbl[i] = *(const uint2*)(g_Blo + n * 256 + kb + u * 4);
        }
    };

    loadA(0);
    loadB(0);

    for (int t = 0; t < 8; t++) {
        int kb = t * 32;
        __syncthreads();  // prior compute done reading smem
        // ---- store staged regs -> smem ----
#pragma unroll
        for (int i = 0; i < 4; i++) {
            int idx = tid + i * 256;
            int r = idx >> 3, u = idx & 7;
            *(uint2*)&As_hi[r][u * 4] = rah[i];
            *(uint2*)&As_lo[r][u * 4] = ral[i];
        }
#pragma unroll
        for (int i = 0; i < BITER; i++) {
            int idx = tid + i * 256;
            int n = idx >> 3, u = idx & 7;
            *(uint2*)&Bs_hi[n][u * 4] = rbh[i];
            *(uint2*)&Bs_lo[n][u * 4] = rbl[i];
        }
        __syncthreads();
        if (t < 7) { loadA(kb + 32); loadB(kb + 32); }  // prefetch overlaps compute

        // ---- compute: 2 k16 steps ----
#pragma unroll
        for (int kk = 0; kk < 2; kk++) {
            int k0 = kk * 16;
            uint32_t a_hi[2][4], a_lo[2][4];
#pragma unroll
            for (int mi = 0; mi < 2; mi++) {
                int r = wm * 32 + mi * 16 + qrow;
                a_hi[mi][0] = *(const uint32_t*)&As_hi[r][k0 + qk2];
                a_hi[mi][1] = *(const uint32_t*)&As_hi[r + 8][k0 + qk2];
                a_hi[mi][2] = *(const uint32_t*)&As_hi[r][k0 + qk2 + 8];
                a_hi[mi][3] = *(const uint32_t*)&As_hi[r + 8][k0 + qk2 + 8];
                a_lo[mi][0] = *(const uint32_t*)&As_lo[r][k0 + qk2];
                a_lo[mi][1] = *(const uint32_t*)&As_lo[r + 8][k0 + qk2];
                a_lo[mi][2] = *(const uint32_t*)&As_lo[r][k0 + qk2 + 8];
                a_lo[mi][3] = *(const uint32_t*)&As_lo[r + 8][k0 + qk2 + 8];
            }
#pragma unroll
            for (int ni = 0; ni < NF; ni++) {
                int n = wn * HN + ni * 8 + qrow;
                uint32_t b_hi[2], b_lo[2];
                b_hi[0] = *(const uint32_t*)&Bs_hi[n][k0 + qk2];
                b_hi[1] = *(const uint32_t*)&Bs_hi[n][k0 + qk2 + 8];
                b_lo[0] = *(const uint32_t*)&Bs_lo[n][k0 + qk2];
                b_lo[1] = *(const uint32_t*)&Bs_lo[n][k0 + qk2 + 8];
#pragma unroll
                for (int mi = 0; mi < 2; mi++) {
                    mma16816(c[mi][ni], a_hi[mi], b_hi);
                    mma16816(c[mi][ni], a_hi[mi], b_lo);
                    mma16816(c[mi][ni], a_lo[mi], b_hi);
                }
            }
        }
    }

    // ---- epilogue ----
#pragma unroll
    for (int mi = 0; mi < 2; mi++) {
        int r0 = rowBase + wm * 32 + mi * 16 + qrow;
#pragma unroll
        for (int ni = 0; ni < NF; ni++) {
            int col = wn * HN + ni * 8 + qk2;
            float b0 = (col < NOUT) ? bias[col] : 0.f;
            float b1 = (col + 1 < NOUT) ? bias[col + 1] : 0.f;
            float v0 = c[mi][ni][0] + b0, v1 = c[mi][ni][1] + b1;
            float v2 = c[mi][ni][2] + b0, v3 = c[mi][ni][3] + b1;
            if (RELU) {
                v0 = fmaxf(v0, 0.f); v1 = fmaxf(v1, 0.f);
                v2 = fmaxf(v2, 0.f); v3 = fmaxf(v3, 0.f);
            }
            if (OUTP) {
                if (r0 < N_NODES) {
                    uint32_t hi, lo;
                    split2(v0, v1, hi, lo);
                    *(uint32_t*)(outHi + (size_t)r0 * 128 + col) = hi;
                    *(uint32_t*)(outLo + (size_t)r0 * 128 + col) = lo;
                }
                if (r0 + 8 < N_NODES) {
                    uint32_t hi, lo;
                    split2(v2, v3, hi, lo);
                    *(uint32_t*)(outHi + (size_t)(r0 + 8) * 128 + col) = hi;
                    *(uint32_t*)(outLo + (size_t)(r0 + 8) * 128 + col) = lo;
                }
            } else {
                if (r0 < N_NODES) {
                    if (col < NOUT)     outf[(size_t)r0 * NOUT + col]     = v0;
                    if (col + 1 < NOUT) outf[(size_t)r0 * NOUT + col + 1] = v1;
                }
                if (r0 + 8 < N_NODES) {
                    if (col < NOUT)     outf[(size_t)(r0 + 8) * NOUT + col]     = v2;
                    if (col + 1 < NOUT) outf[(size_t)(r0 + 8) * NOUT + col + 1] = v3;
                }
            }
        }
    }
}

// ---------------- launch ----------------

extern "C" void kernel_launch(void* const* d_in, const int* in_sizes, int n_in,
                              void* d_out, int out_size) {
    const float* x   = (const float*)d_in[0];
    const int*   src = (const int*)d_in[1];
    const int*   dst = (const int*)d_in[2];
    const float* ws1 = (const float*)d_in[3];
    const float* wn1 = (const float*)d_in[4];
    const float* b1  = (const float*)d_in[5];
    const float* ws2 = (const float*)d_in[6];
    const float* wn2 = (const float*)d_in[7];
    const float* b2  = (const float*)d_in[8];
    const float* ws3 = (const float*)d_in[9];
    const float* wn3 = (const float*)d_in[10];
    const float* b3  = (const float*)d_in[11];
    float* out = (float*)d_out;

    void *p0h, *p0l, *p1h, *p1l;
    cudaGetSymbolAddress(&p0h, g_f0hi);
    cudaGetSymbolAddress(&p0l, g_f0lo);
    cudaGetSymbolAddress(&p1h, g_f1hi);
    cudaGetSymbolAddress(&p1l, g_f1lo);
    __nv_bfloat16* f0hi = (__nv_bfloat16*)p0h;
    __nv_bfloat16* f0lo = (__nv_bfloat16*)p0l;
    __nv_bfloat16* f1hi = (__nv_bfloat16*)p1h;
    __nv_bfloat16* f1lo = (__nv_bfloat16*)p1l;

    const int EB = (N_EDGES + 255) / 256;
    const int ZB = (N_NODES / 4 + 255) / 256;
    const int AGG_B = (N_NODES * 32 + 255) / 256;
    const int GEMM_B = (N_NODES + 127) / 128;

    // CSR build
    zero_cursor_k<<<ZB, 256>>>();
    count_k<<<EB, 256>>>(dst);
    scan_k<<<1, 1024>>>();
    bucket_k<<<EB, 256>>>(src, dst);

    // Layer 1: A self = x (fp32), mean from fp32 gather; out packed
    prepB_k<<<(128 * 256 + 255) / 256, 256>>>(ws1, wn1, 128, 128);
    agg_k<true><<<AGG_B, 256>>>(x, nullptr, nullptr);
    gemm_mma<128, 128, true, true, true><<<GEMM_B, 256>>>(
        x, nullptr, nullptr, b1, nullptr, f0hi, f0lo);

    // Layer 2: packed A, packed gather; out packed
    prepB_k<<<(128 * 256 + 255) / 256, 256>>>(ws2, wn2, 128, 128);
    agg_k<false><<<AGG_B, 256>>>(nullptr, f0hi, f0lo);
    gemm_mma<128, 128, true, false, true><<<GEMM_B, 256>>>(
        nullptr, f0hi, f0lo, b2, nullptr, f1hi, f1lo);

    // Layer 3: packed A, packed gather; fp32 out
    prepB_k<<<(64 * 256 + 255) / 256, 256>>>(ws3, wn3, N_OUT, 64);
    agg_k<false><<<AGG_B, 256>>>(nullptr, f1hi, f1lo);
    gemm_mma<64, N_OUT, false, false, false><<<GEMM_B, 256>>>(
        nullptr, f1hi, f1lo, b3, out, nullptr, nullptr);
}

// round 10
// speedup vs baseline: 1.0131x; 1.0131x over previous
#include <cuda_runtime.h>
#include <cuda_bf16.h>
#include <cstdint>

#define N_NODES 50000
#define DIM 128
#define N_EDGES 800000
#define N_OUT 47

// ---------------- scratch (device globals; no allocation allowed) ----------------
// features stored as split bf16: value = hi + lo  (hi = bf16(x), lo = bf16(x - hi))
__device__ __align__(16) __nv_bfloat16 g_f0hi[N_NODES * DIM];
__device__ __align__(16) __nv_bfloat16 g_f0lo[N_NODES * DIM];
__device__ __align__(16) __nv_bfloat16 g_f1hi[N_NODES * DIM];
__device__ __align__(16) __nv_bfloat16 g_f1lo[N_NODES * DIM];
__device__ __align__(16) __nv_bfloat16 g_mhi[N_NODES * DIM];
__device__ __align__(16) __nv_bfloat16 g_mlo[N_NODES * DIM];
__device__ int   g_rowptr[N_NODES + 1];
__device__ __align__(16) int g_cursor[N_NODES];
__device__ int   g_esrc[N_EDGES];
__device__ __align__(16) __nv_bfloat16 g_Bhi[128 * 256];  // weights hi, row-major [N][256]
__device__ __align__(16) __nv_bfloat16 g_Blo[128 * 256];  // weights lo

// ---------------- helpers ----------------

__device__ __forceinline__ uint32_t pack_bf16(__nv_bfloat16 l, __nv_bfloat16 h) {
    return ((uint32_t)__bfloat16_as_ushort(h) << 16) | __bfloat16_as_ushort(l);
}
__device__ __forceinline__ float bf_lo(uint32_t w) { return __uint_as_float(w << 16); }
__device__ __forceinline__ float bf_hi(uint32_t w) { return __uint_as_float(w & 0xFFFF0000u); }

__device__ __forceinline__ void split2(float v0, float v1, uint32_t& hi, uint32_t& lo) {
    __nv_bfloat16 h0 = __float2bfloat16(v0), h1 = __float2bfloat16(v1);
    __nv_bfloat16 l0 = __float2bfloat16(v0 - __bfloat162float(h0));
    __nv_bfloat16 l1 = __float2bfloat16(v1 - __bfloat162float(h1));
    hi = pack_bf16(h0, h1);
    lo = pack_bf16(l0, l1);
}

__device__ __forceinline__ void ldsm4(uint32_t* r, uint32_t addr) {
    asm volatile("ldmatrix.sync.aligned.m8n8.x4.shared.b16 {%0,%1,%2,%3}, [%4];"
        : "=r"(r[0]), "=r"(r[1]), "=r"(r[2]), "=r"(r[3]) : "r"(addr));
}

// ---------------- CSR build (by dst) ----------------

__global__ void zero_cursor_k() {
    int i = blockIdx.x * blockDim.x + threadIdx.x;
    if (i < N_NODES / 4) ((int4*)g_cursor)[i] = make_int4(0, 0, 0, 0);
}
__global__ void count_k(const int* __restrict__ dst) {
    int e = blockIdx.x * blockDim.x + threadIdx.x;
    if (e < N_EDGES) atomicAdd(&g_cursor[dst[e]], 1);
}
__global__ void scan_k() {
    __shared__ int ssum[1024];
    int t = threadIdx.x;
    const int CH = (N_NODES + 1023) / 1024;
    int base = t * CH;
    int s = 0;
    for (int i = 0; i < CH; i++) { int idx = base + i; if (idx < N_NODES) s += g_cursor[idx]; }
    ssum[t] = s;
    __syncthreads();
    for (int off = 1; off < 1024; off <<= 1) {
        int v = 0;
        if (t >= off) v = ssum[t - off];
        __syncthreads();
        if (t >= off) ssum[t] += v;
        __syncthreads();
    }
    int run = (t == 0) ? 0 : ssum[t - 1];
    for (int i = 0; i < CH; i++) {
        int idx = base + i;
        if (idx < N_NODES) {
            int c = g_cursor[idx];
            g_rowptr[idx] = run;
            g_cursor[idx] = run;
            run += c;
        }
    }
    if (t == 0) g_rowptr[N_NODES] = N_EDGES;
}
__global__ void bucket_k(const int* __restrict__ src, const int* __restrict__ dst) {
    int e = blockIdx.x * blockDim.x + threadIdx.x;
    if (e < N_EDGES) {
        int pos = atomicAdd(&g_cursor[dst[e]], 1);
        g_esrc[pos] = src[e];
    }
}

// ---------------- mean aggregation: one warp per node; writes packed hi/lo mean ----------------

template <bool GF32>
__global__ void agg_k(const float* __restrict__ xf,
                      const __nv_bfloat16* __restrict__ hhi,
                      const __nv_bfloat16* __restrict__ hlo) {
    int gt = blockIdx.x * blockDim.x + threadIdx.x;
    int node = gt >> 5, lane = gt & 31;
    if (node >= N_NODES) return;
    int beg = g_rowptr[node], end = g_rowptr[node + 1];
    float a0 = 0.f, a1 = 0.f, a2 = 0.f, a3 = 0.f;
    float c0 = 0.f, c1 = 0.f, c2 = 0.f, c3 = 0.f;
    int j = beg;
    if (GF32) {
        for (; j + 1 < end; j += 2) {
            int s0 = g_esrc[j], s1 = g_esrc[j + 1];
            float4 v0 = *(const float4*)(xf + (size_t)s0 * DIM + lane * 4);
            float4 v1 = *(const float4*)(xf + (size_t)s1 * DIM + lane * 4);
            a0 += v0.x; a1 += v0.y; a2 += v0.z; a3 += v0.w;
            c0 += v1.x; c1 += v1.y; c2 += v1.z; c3 += v1.w;
        }
        if (j < end) {
            int s0 = g_esrc[j];
            float4 v0 = *(const float4*)(xf + (size_t)s0 * DIM + lane * 4);
            a0 += v0.x; a1 += v0.y; a2 += v0.z; a3 += v0.w;
        }
    } else {
        for (; j + 1 < end; j += 2) {
            int s0 = g_esrc[j], s1 = g_esrc[j + 1];
            uint2 h0 = *(const uint2*)(hhi + (size_t)s0 * DIM + lane * 4);
            uint2 l0 = *(const uint2*)(hlo + (size_t)s0 * DIM + lane * 4);
            uint2 h1 = *(const uint2*)(hhi + (size_t)s1 * DIM + lane * 4);
            uint2 l1 = *(const uint2*)(hlo + (size_t)s1 * DIM + lane * 4);
            a0 += bf_lo(h0.x) + bf_lo(l0.x); a1 += bf_hi(h0.x) + bf_hi(l0.x);
            a2 += bf_lo(h0.y) + bf_lo(l0.y); a3 += bf_hi(h0.y) + bf_hi(l0.y);
            c0 += bf_lo(h1.x) + bf_lo(l1.x); c1 += bf_hi(h1.x) + bf_hi(l1.x);
            c2 += bf_lo(h1.y) + bf_lo(l1.y); c3 += bf_hi(h1.y) + bf_hi(l1.y);
        }
        if (j < end) {
            int s0 = g_esrc[j];
            uint2 h0 = *(const uint2*)(hhi + (size_t)s0 * DIM + lane * 4);
            uint2 l0 = *(const uint2*)(hlo + (size_t)s0 * DIM + lane * 4);
            a0 += bf_lo(h0.x) + bf_lo(l0.x); a1 += bf_hi(h0.x) + bf_hi(l0.x);
            a2 += bf_lo(h0.y) + bf_lo(l0.y); a3 += bf_hi(h0.y) + bf_hi(l0.y);
        }
    }
    float inv = 1.f / fmaxf((float)(end - beg), 1.f);
    a0 = (a0 + c0) * inv; a1 = (a1 + c1) * inv;
    a2 = (a2 + c2) * inv; a3 = (a3 + c3) * inv;
    uint32_t h01, l01, h23, l23;
    split2(a0, a1, h01, l01);
    split2(a2, a3, h23, l23);
    size_t off = (size_t)node * DIM + lane * 4;
    *(uint32_t*)(g_mhi + off) = h01;
    *(uint32_t*)(g_mhi + off + 2) = h23;
    *(uint32_t*)(g_mlo + off) = l01;
    *(uint32_t*)(g_mlo + off + 2) = l23;
}

// ---------------- B prep: W[n][k] -> hi/lo bf16 row-major [NT][256] ----------------

__global__ void prepB_k(const float* __restrict__ ws, const float* __restrict__ wn,
                        int nout, int NT) {
    int idx = blockIdx.x * blockDim.x + threadIdx.x;
    if (idx >= NT * 256) return;
    int n = idx / 256, k = idx % 256;
    float v = 0.f;
    if (n < nout) v = (k < 128) ? ws[n * 128 + k] : wn[n * 128 + (k - 128)];
    __nv_bfloat16 h = __float2bfloat16(v);
    __nv_bfloat16 l = __float2bfloat16(v - __bfloat162float(h));
    g_Bhi[idx] = h;
    g_Blo[idx] = l;
}

// ---------------- mma.sync split-bf16 GEMM ----------------
// 256 thr = 8 warps (4m x 2n). CTA tile 128 x BN, BK=32. m16n8k16 bf16 HMMA, fp32 accum.
// 3 passes: Ahi*Bhi + Ahi*Blo + Alo*Bhi. Frag loads via ldmatrix.x4; reg prefetch staging.

__device__ __forceinline__ void mma16816(float* c, const uint32_t* a, const uint32_t* b) {
    asm volatile(
        "mma.sync.aligned.m16n8k16.row.col.f32.bf16.bf16.f32 "
        "{%0,%1,%2,%3}, {%4,%5,%6,%7}, {%8,%9}, {%0,%1,%2,%3};"
        : "+f"(c[0]), "+f"(c[1]), "+f"(c[2]), "+f"(c[3])
        : "r"(a[0]), "r"(a[1]), "r"(a[2]), "r"(a[3]), "r"(b[0]), "r"(b[1]));
}

#define BKP 40  // padded row: 32 bf16 + 8 (stride 80B -> conflict-free LDS/LDSM)

template <int BN, int NOUT, bool RELU, bool L1, bool OUTP>
__global__ void __launch_bounds__(256) gemm_mma(
    const float* __restrict__ xf,
    const __nv_bfloat16* __restrict__ Ahi, const __nv_bfloat16* __restrict__ Alo,
    const float* __restrict__ bias,
    float* __restrict__ outf,
    __nv_bfloat16* __restrict__ outHi, __nv_bfloat16* __restrict__ outLo) {
    constexpr int HN = BN / 2;
    constexpr int NF = HN / 8;
    constexpr int BITER = BN / 32;  // B uint2s per thread
    __shared__ __align__(16) uint16_t As_hi[128][BKP];
    __shared__ __align__(16) uint16_t As_lo[128][BKP];
    __shared__ __align__(16) uint16_t Bs_hi[BN][BKP];
    __shared__ __align__(16) uint16_t Bs_lo[BN][BKP];

    int tid = threadIdx.x;
    int warp = tid >> 5, lane = tid & 31;
    int wm = warp & 3, wn = warp >> 2;
    int qrow = lane >> 2, qk2 = (lane & 3) * 2;
    int rowBase = blockIdx.x * 128;

    float c[2][NF][4];
#pragma unroll
    for (int mi = 0; mi < 2; mi++)
#pragma unroll
        for (int ni = 0; ni < NF; ni++)
#pragma unroll
            for (int j = 0; j < 4; j++) c[mi][ni][j] = 0.f;

    // ldmatrix lane-address precompute:
    // A x4: g0->(r+l, k0), g1->(r+8+l, k0), g2->(r+l, k0+8), g3->(r+8+l, k0+8)
    // B x4: g0->(n+l, k0), g1->(n+l, k0+8), g2->(n+8+l, k0), g3->(n+8+l, k0+8)
    int g = lane >> 3, l = lane & 7;
    uint32_t aoff = (uint32_t)(((wm * 32 + ((g & 1) << 3) + l) * BKP + ((g >> 1) << 3)) * 2);
    uint32_t boff = (uint32_t)(((wn * HN + ((g & 2) << 2) + l) * BKP + ((g & 1) << 3)) * 2);
    uint32_t aAddrHi = (uint32_t)__cvta_generic_to_shared(As_hi) + aoff;
    uint32_t aAddrLo = (uint32_t)__cvta_generic_to_shared(As_lo) + aoff;
    uint32_t bAddrHi = (uint32_t)__cvta_generic_to_shared(Bs_hi) + boff;
    uint32_t bAddrLo = (uint32_t)__cvta_generic_to_shared(Bs_lo) + boff;

    uint2 rah[4], ral[4], rbh[BITER], rbl[BITER];

    auto loadA = [&](int kb) {
        if (L1 && kb < 128) {
#pragma unroll
            for (int i = 0; i < 4; i++) {
                int idx = tid + i * 256;
                int r = idx >> 3, u = idx & 7;
                int gr = rowBase + r;
                if (gr >= N_NODES) gr = N_NODES - 1;
                float4 v = *(const float4*)(xf + (size_t)gr * 128 + kb + u * 4);
                split2(v.x, v.y, rah[i].x, ral[i].x);
                split2(v.z, v.w, rah[i].y, ral[i].y);
            }
        } else {
            const __nv_bfloat16* sh = (kb < 128) ? Ahi + kb : g_mhi + (kb - 128);
            const __nv_bfloat16* sl = (kb < 128) ? Alo + kb : g_mlo + (kb - 128);
#pragma unroll
            for (int i = 0; i < 4; i++) {
                int idx = tid + i * 256;
                int r = idx >> 3, u = idx & 7;
                int gr = rowBase + r;
                if (gr >= N_NODES) gr = N_NODES - 1;
                rah[i] = *(const uint2*)(sh + (size_t)gr * 128 + u * 4);
                ral[i] = *(const uint2*)(sl + (size_t)gr * 128 + u * 4);
            }
        }
    };
    auto loadB = [&](int kb) {
#pragma unroll
        for (int i = 0; i < BITER; i++) {
            int idx = tid + i * 256;
            int n = idx >> 3, u = idx & 7;
            rbh[i] = *(const uint2*)(g_Bhi + n * 256 + kb + u * 4);
            rbl[i] = *(const uint2*)(g_Blo + n * 256 + kb + u * 4);
        }
    };

    loadA(0);
    loadB(0);

    for (int t = 0; t < 8; t++) {
        int kb = t * 32;
        __syncthreads();  // prior compute done reading smem
#pragma unroll
        for (int i = 0; i < 4; i++) {
            int idx = tid + i * 256;
            int r = idx >> 3, u = idx & 7;
            *(uint2*)&As_hi[r][u * 4] = rah[i];
            *(uint2*)&As_lo[r][u * 4] = ral[i];
        }
#pragma unroll
        for (int i = 0; i < BITER; i++) {
            int idx = tid + i * 256;
            int n = idx >> 3, u = idx & 7;
            *(uint2*)&Bs_hi[n][u * 4] = rbh[i];
            *(uint2*)&Bs_lo[n][u * 4] = rbl[i];
        }
        __syncthreads();
        if (t < 7) { loadA(kb + 32); loadB(kb + 32); }  // prefetch overlaps compute

        // ---- compute: 2 k16 steps, ldmatrix frag loads ----
#pragma unroll
        for (int kk = 0; kk < 2; kk++) {
            uint32_t koff = kk * 32;  // 16 cols * 2 B
            uint32_t a_hi[2][4], a_lo[2][4];
#pragma unroll
            for (int mi = 0; mi < 2; mi++) {
                ldsm4(a_hi[mi], aAddrHi + mi * (16 * BKP * 2) + koff);
                ldsm4(a_lo[mi], aAddrLo + mi * (16 * BKP * 2) + koff);
            }
#pragma unroll
            for (int nj = 0; nj < NF / 2; nj++) {
                uint32_t bh[4], bl[4];
                ldsm4(bh, bAddrHi + nj * (16 * BKP * 2) + koff);
                ldsm4(bl, bAddrLo + nj * (16 * BKP * 2) + koff);
#pragma unroll
                for (int hh = 0; hh < 2; hh++) {
                    int ni = nj * 2 + hh;
#pragma unroll
                    for (int mi = 0; mi < 2; mi++) {
                        mma16816(c[mi][ni], a_hi[mi], bh + hh * 2);
                        mma16816(c[mi][ni], a_hi[mi], bl + hh * 2);
                        mma16816(c[mi][ni], a_lo[mi], bh + hh * 2);
                    }
                }
            }
        }
    }

    // ---- epilogue ----
#pragma unroll
    for (int mi = 0; mi < 2; mi++) {
        int r0 = rowBase + wm * 32 + mi * 16 + qrow;
#pragma unroll
        for (int ni = 0; ni < NF; ni++) {
            int col = wn * HN + ni * 8 + qk2;
            float b0 = (col < NOUT) ? bias[col] : 0.f;
            float b1 = (col + 1 < NOUT) ? bias[col + 1] : 0.f;
            float v0 = c[mi][ni][0] + b0, v1 = c[mi][ni][1] + b1;
            float v2 = c[mi][ni][2] + b0, v3 = c[mi][ni][3] + b1;
            if (RELU) {
                v0 = fmaxf(v0, 0.f); v1 = fmaxf(v1, 0.f);
                v2 = fmaxf(v2, 0.f); v3 = fmaxf(v3, 0.f);
            }
            if (OUTP) {
                if (r0 < N_NODES) {
                    uint32_t hi, lo;
                    split2(v0, v1, hi, lo);
                    *(uint32_t*)(outHi + (size_t)r0 * 128 + col) = hi;
                    *(uint32_t*)(outLo + (size_t)r0 * 128 + col) = lo;
                }
                if (r0 + 8 < N_NODES) {
                    uint32_t hi, lo;
                    split2(v2, v3, hi, lo);
                    *(uint32_t*)(outHi + (size_t)(r0 + 8) * 128 + col) = hi;
                    *(uint32_t*)(outLo + (size_t)(r0 + 8) * 128 + col) = lo;
                }
            } else {
                if (r0 < N_NODES) {
                    if (col < NOUT)     outf[(size_t)r0 * NOUT + col]     = v0;
                    if (col + 1 < NOUT) outf[(size_t)r0 * NOUT + col + 1] = v1;
                }
                if (r0 + 8 < N_NODES) {
                    if (col < NOUT)     outf[(size_t)(r0 + 8) * NOUT + col]     = v2;
                    if (col + 1 < NOUT) outf[(size_t)(r0 + 8) * NOUT + col + 1] = v3;
                }
            }
        }
    }
}

// ---------------- launch ----------------

extern "C" void kernel_launch(void* const* d_in, const int* in_sizes, int n_in,
                              void* d_out, int out_size) {
    const float* x   = (const float*)d_in[0];
    const int*   src = (const int*)d_in[1];
    const int*   dst = (const int*)d_in[2];
    const float* ws1 = (const float*)d_in[3];
    const float* wn1 = (const float*)d_in[4];
    const float* b1  = (const float*)d_in[5];
    const float* ws2 = (const float*)d_in[6];
    const float* wn2 = (const float*)d_in[7];
    const float* b2  = (const float*)d_in[8];
    const float* ws3 = (const float*)d_in[9];
    const float* wn3 = (const float*)d_in[10];
    const float* b3  = (const float*)d_in[11];
    float* out = (float*)d_out;

    void *p0h, *p0l, *p1h, *p1l;
    cudaGetSymbolAddress(&p0h, g_f0hi);
    cudaGetSymbolAddress(&p0l, g_f0lo);
    cudaGetSymbolAddress(&p1h, g_f1hi);
    cudaGetSymbolAddress(&p1l, g_f1lo);
    __nv_bfloat16* f0hi = (__nv_bfloat16*)p0h;
    __nv_bfloat16* f0lo = (__nv_bfloat16*)p0l;
    __nv_bfloat16* f1hi = (__nv_bfloat16*)p1h;
    __nv_bfloat16* f1lo = (__nv_bfloat16*)p1l;

    const int EB = (N_EDGES + 255) / 256;
    const int ZB = (N_NODES / 4 + 255) / 256;
    const int AGG_B = (N_NODES * 32 + 255) / 256;
    const int GEMM_B = (N_NODES + 127) / 128;

    // CSR build
    zero_cursor_k<<<ZB, 256>>>();
    count_k<<<EB, 256>>>(dst);
    scan_k<<<1, 1024>>>();
    bucket_k<<<EB, 256>>>(src, dst);

    // Layer 1: A self = x (fp32), mean from fp32 gather; out packed
    prepB_k<<<(128 * 256 + 255) / 256, 256>>>(ws1, wn1, 128, 128);
    agg_k<true><<<AGG_B, 256>>>(x, nullptr, nullptr);
    gemm_mma<128, 128, true, true, true><<<GEMM_B, 256>>>(
        x, nullptr, nullptr, b1, nullptr, f0hi, f0lo);

    // Layer 2: packed A, packed gather; out packed
    prepB_k<<<(128 * 256 + 255) / 256, 256>>>(ws2, wn2, 128, 128);
    agg_k<false><<<AGG_B, 256>>>(nullptr, f0hi, f0lo);
    gemm_mma<128, 128, true, false, true><<<GEMM_B, 256>>>(
        nullptr, f0hi, f0lo, b2, nullptr, f1hi, f1lo);

    // Layer 3: packed A, packed gather; fp32 out
    prepB_k<<<(64 * 256 + 255) / 256, 256>>>(ws3, wn3, N_OUT, 64);
    agg_k<false><<<AGG_B, 256>>>(nullptr, f1hi, f1lo);
    gemm_mma<64, N_OUT, false, false, false><<<GEMM_B, 256>>>(
        nullptr, f1hi, f1lo, b3, out, nullptr, nullptr);
}